// round 9
// baseline (speedup 1.0000x reference)
#include <cuda_runtime.h>
#include <cuda_bf16.h>
#include <cuda_fp16.h>
#include <cstdint>

#define NUM_USERS 100000
#define NUM_ITEMS 50000
#define LATENT    64
#define N_EDGES   600000
#define BATCH     4096
#define N_NODES   (NUM_USERS + NUM_ITEMS)          // 150000
#define TOT_F     (N_NODES * LATENT)               // 9,600,000
#define USER_F    (NUM_USERS * LATENT)
#define N_DIR     (2 * N_EDGES)
#define N_PART    ((N_NODES + 255) / 256)          // 586
#define EPT       4                                 // edges per thread (atomic kernels)
#define N_ETHR    ((N_EDGES + EPT - 1) / EPT)       // 150000

// ---------------- scratch (device globals) ----------------------------------
__device__ __half g_x0h[TOT_F];                    // fp16 x0 (19.2 MB)
__device__ __half g_z[3 * TOT_F];                  // z_1..z_3 fp16 (57.6 MB)
__device__ int    g_degi  [N_NODES];               // zero at entry (reset by spmm1h)
__device__ float  g_inv   [N_NODES];               // 1/sqrt(deg)
__device__ float  g_inv2  [N_NODES];               // 1/deg
__device__ int    g_part  [N_PART];
__device__ int    g_rowptr[N_NODES + 1];           // +1 sentinel = N_DIR
__device__ int    g_cursor[N_NODES];
__device__ int    g_adj   [N_DIR];                 // src index only

// ---------------- kernels ---------------------------------------------------

// Fused: degree atomics (4 edges/thread for MLP) + fp16 cast of x0.
// Relies on g_degi == 0 at entry (loader zero-init; k_spmm1h resets per run).
__global__ void k_deg_conv(const int* __restrict__ eu, const int* __restrict__ ei,
                           const float* __restrict__ uemb, const float* __restrict__ iemb) {
    int i = blockIdx.x * blockDim.x + threadIdx.x;   // 0 .. 1.2M-1
    const int n8 = TOT_F / 8;                        // 1,200,000
    if (i < n8) {
        int base = i * 8;
        const float4* src = (base < USER_F)
            ? reinterpret_cast<const float4*>(uemb + base)
            : reinterpret_cast<const float4*>(iemb + (base - USER_F));
        float4 a = src[0];
        float4 b = src[1];
        uint4 pack;
        __half2* h = reinterpret_cast<__half2*>(&pack);
        h[0] = __floats2half2_rn(a.x, a.y);
        h[1] = __floats2half2_rn(a.z, a.w);
        h[2] = __floats2half2_rn(b.x, b.y);
        h[3] = __floats2half2_rn(b.z, b.w);
        reinterpret_cast<uint4*>(g_x0h)[i] = pack;
    }
    if (i < N_ETHR) {
        int e0 = i * EPT;
        int n  = min(EPT, N_EDGES - e0);
        int us[EPT], vs[EPT];
        #pragma unroll
        for (int k = 0; k < EPT; k++) {
            int e = e0 + min(k, n - 1);              // clamp (dup atomics avoided below)
            us[k] = eu[e];
            vs[k] = ei[e];
        }
        #pragma unroll
        for (int k = 0; k < EPT; k++)
            if (k < n) atomicAdd(&g_degi[us[k]], 1);
        #pragma unroll
        for (int k = 0; k < EPT; k++)
            if (k < n) atomicAdd(&g_degi[NUM_USERS + vs[k]], 1);
    }
}

// per-256-chunk degree partial sums only
__global__ void k_part() {
    __shared__ int s[256];
    int t = threadIdx.x;
    int n = blockIdx.x * 256 + t;
    s[t] = (n < N_NODES) ? g_degi[n] : 0;
    __syncthreads();
    for (int off = 128; off > 0; off >>= 1) {
        if (t < off) s[t] += s[t + off];
        __syncthreads();
    }
    if (t == 0) g_part[blockIdx.x] = s[0];
}

// rowptr + inv + inv2: block sums partials before it, then local 256-scan.
__global__ void k_rowptr() {
    __shared__ int s[256];
    __shared__ int base_s;
    int t   = threadIdx.x;
    int bid = blockIdx.x;

    int p = 0;
    for (int i = t; i < bid; i += 256) p += g_part[i];
    s[t] = p;
    __syncthreads();
    for (int off = 128; off > 0; off >>= 1) {
        if (t < off) s[t] += s[t + off];
        __syncthreads();
    }
    if (t == 0) base_s = s[0];
    __syncthreads();
    int base = base_s;

    int n = bid * 256 + t;
    int v = (n < N_NODES) ? g_degi[n] : 0;
    if (n < N_NODES) {
        float fd = (float)v;
        g_inv [n] = (v > 0) ? rsqrtf(fd)  : 0.f;
        g_inv2[n] = (v > 0) ? (1.0f / fd) : 0.f;
    }
    s[t] = v;
    __syncthreads();
    for (int off = 1; off < 256; off <<= 1) {
        int a = (t >= off) ? s[t - off] : 0;
        __syncthreads();
        s[t] += a;
        __syncthreads();
    }
    if (n < N_NODES) {
        int rp = base + s[t] - v;
        g_rowptr[n] = rp;
        g_cursor[n] = rp;
        if (n == N_NODES - 1) g_rowptr[N_NODES] = N_DIR;
    }
}

// CSR fill, 4 edges per thread (8 independent atomics in flight)
__global__ void k_fill(const int* __restrict__ eu, const int* __restrict__ ei) {
    int i = blockIdx.x * blockDim.x + threadIdx.x;
    if (i >= N_ETHR) return;
    int e0 = i * EPT;
    int n  = min(EPT, N_EDGES - e0);

    int us[EPT], vs[EPT], pu[EPT], pv[EPT];
    #pragma unroll
    for (int k = 0; k < EPT; k++) {
        int e = e0 + min(k, n - 1);
        us[k] = eu[e];
        vs[k] = NUM_USERS + ei[e];
    }
    #pragma unroll
    for (int k = 0; k < EPT; k++)
        if (k < n) pu[k] = atomicAdd(&g_cursor[us[k]], 1);
    #pragma unroll
    for (int k = 0; k < EPT; k++)
        if (k < n) pv[k] = atomicAdd(&g_cursor[vs[k]], 1);
    #pragma unroll
    for (int k = 0; k < EPT; k++)
        if (k < n) g_adj[pu[k]] = vs[k];
    #pragma unroll
    for (int k = 0; k < EPT; k++)
        if (k < n) g_adj[pv[k]] = us[k];
}

// Layer 1: z1[dst] = inv2[dst] * sum_src inv[src] * x0h[src]
// 8 lanes per row; lane owns 8 halves (uint4). fp32 accumulation.
// Also resets g_degi for the next graph replay.
__global__ void k_spmm1h(const __half* __restrict__ x, __half* __restrict__ y) {
    int gid = blockIdx.x * blockDim.x + threadIdx.x;
    if (gid < N_NODES) g_degi[gid] = 0;              // reset for next replay
    int row = gid >> 3;
    int sub = gid & 7;
    if (row >= N_NODES) return;

    int beg = g_rowptr[row];
    int cnt = g_rowptr[row + 1] - beg;
    float acc[8] = {0.f, 0.f, 0.f, 0.f, 0.f, 0.f, 0.f, 0.f};

    auto accum = [&](uint4 v, float ws) {
        const __half2* h = reinterpret_cast<const __half2*>(&v);
        #pragma unroll
        for (int q = 0; q < 4; q++) {
            float2 f = __half22float2(h[q]);
            acc[2 * q]     += ws * f.x;
            acc[2 * q + 1] += ws * f.y;
        }
    };

    int j = 0;
    for (; j + 1 < cnt; j += 2) {
        int s0 = g_adj[beg + j + 0];
        int s1 = g_adj[beg + j + 1];
        float w0 = g_inv[s0];
        float w1 = g_inv[s1];
        uint4 v0 = reinterpret_cast<const uint4*>(x + (size_t)s0 * LATENT)[sub];
        uint4 v1 = reinterpret_cast<const uint4*>(x + (size_t)s1 * LATENT)[sub];
        accum(v0, w0); accum(v1, w1);
    }
    if (j < cnt) {
        int s0 = g_adj[beg + j];
        float w0 = g_inv[s0];
        uint4 v0 = reinterpret_cast<const uint4*>(x + (size_t)s0 * LATENT)[sub];
        accum(v0, w0);
    }

    float s = g_inv2[row];
    uint4 outp;
    __half2* oh = reinterpret_cast<__half2*>(&outp);
    #pragma unroll
    for (int q = 0; q < 4; q++)
        oh[q] = __floats2half2_rn(acc[2 * q] * s, acc[2 * q + 1] * s);
    reinterpret_cast<uint4*>(y + (size_t)row * LATENT)[sub] = outp;
}

// Layers 2..3: z_{l+1}[dst] = inv2[dst] * sum_src z_l[src]   (fp16 in/out)
__global__ void k_spmmN(const __half* __restrict__ x, __half* __restrict__ y) {
    int gid = blockIdx.x * blockDim.x + threadIdx.x;
    int row = gid >> 3;
    int sub = gid & 7;
    if (row >= N_NODES) return;

    int beg = g_rowptr[row];
    int cnt = g_rowptr[row + 1] - beg;
    float acc[8] = {0.f, 0.f, 0.f, 0.f, 0.f, 0.f, 0.f, 0.f};

    auto accum = [&](uint4 v) {
        const __half2* h = reinterpret_cast<const __half2*>(&v);
        #pragma unroll
        for (int q = 0; q < 4; q++) {
            float2 f = __half22float2(h[q]);
            acc[2 * q]     += f.x;
            acc[2 * q + 1] += f.y;
        }
    };

    int j = 0;
    for (; j + 3 < cnt; j += 4) {
        int s0 = g_adj[beg + j + 0];
        int s1 = g_adj[beg + j + 1];
        int s2 = g_adj[beg + j + 2];
        int s3 = g_adj[beg + j + 3];
        uint4 v0 = reinterpret_cast<const uint4*>(x + (size_t)s0 * LATENT)[sub];
        uint4 v1 = reinterpret_cast<const uint4*>(x + (size_t)s1 * LATENT)[sub];
        uint4 v2 = reinterpret_cast<const uint4*>(x + (size_t)s2 * LATENT)[sub];
        uint4 v3 = reinterpret_cast<const uint4*>(x + (size_t)s3 * LATENT)[sub];
        accum(v0); accum(v1); accum(v2); accum(v3);
    }
    for (; j < cnt; j++) {
        int s0 = g_adj[beg + j];
        uint4 v0 = reinterpret_cast<const uint4*>(x + (size_t)s0 * LATENT)[sub];
        accum(v0);
    }

    float s = g_inv2[row];
    uint4 outp;
    __half2* oh = reinterpret_cast<__half2*>(&outp);
    #pragma unroll
    for (int q = 0; q < 4; q++)
        oh[q] = __floats2half2_rn(acc[2 * q] * s, acc[2 * q + 1] * s);
    reinterpret_cast<uint4*>(y + (size_t)row * LATENT)[sub] = outp;
}

// Fused layer-4 + final dot. One 64-thread block per batch pair.
__global__ void k_final(const int* __restrict__ users, const int* __restrict__ items,
                        const float* __restrict__ uemb, const float* __restrict__ iemb,
                        const __half* __restrict__ z1, const __half* __restrict__ z2,
                        const __half* __restrict__ z3,
                        float* __restrict__ out) {
    __shared__ float red[2];
    int b = blockIdx.x;
    int t = threadIdx.x;            // 0..63 = column

    int u  = users[b];
    int it = NUM_USERS + items[b];

    int bu = g_rowptr[u];
    int cu = g_rowptr[u + 1] - bu;
    int bi = g_rowptr[it];
    int ci = g_rowptr[it + 1] - bi;

    float z4u = 0.f;
    for (int j = 0; j < cu; j++) {
        int s = g_adj[bu + j];
        z4u += __half2float(z3[(size_t)s * LATENT + t]);
    }
    z4u *= g_inv2[u];
    size_t ou = (size_t)u * LATENT + t;
    float zu = __half2float(z1[ou]) + __half2float(z2[ou]) + __half2float(z3[ou]) + z4u;
    float su = uemb[ou] + sqrtf((float)cu) * zu;

    float z4i = 0.f;
    for (int j = 0; j < ci; j++) {
        int s = g_adj[bi + j];
        z4i += __half2float(z3[(size_t)s * LATENT + t]);
    }
    z4i *= g_inv2[it];
    size_t oi = (size_t)it * LATENT + t;
    float zi = __half2float(z1[oi]) + __half2float(z2[oi]) + __half2float(z3[oi]) + z4i;
    float si = iemb[(size_t)(it - NUM_USERS) * LATENT + t] + sqrtf((float)ci) * zi;

    float dot = su * si;
    #pragma unroll
    for (int off = 16; off > 0; off >>= 1)
        dot += __shfl_xor_sync(0xffffffffu, dot, off);
    if ((t & 31) == 0) red[t >> 5] = dot;
    __syncthreads();
    if (t == 0) out[b] = (red[0] + red[1]) * (1.0f / 25.0f);
}

// ---------------- launch ----------------------------------------------------
extern "C" void kernel_launch(void* const* d_in, const int* in_sizes, int n_in,
                              void* d_out, int out_size) {
    const int*   users = (const int*)  d_in[0];
    const int*   items = (const int*)  d_in[1];
    const int*   eu    = (const int*)  d_in[2];
    const int*   ei    = (const int*)  d_in[3];
    const float* uemb  = (const float*)d_in[4];
    const float* iemb  = (const float*)d_in[5];
    float*       out   = (float*)d_out;

    const int T = 256;
    const int n8     = TOT_F / 8;                    // 1.2M
    const int gBig   = (n8 + T - 1) / T;
    const int gEThr  = (N_ETHR + T - 1) / T;
    const int gRow8  = (N_NODES * 8 + T - 1) / T;

    static __half* pZ = nullptr; static __half* pX = nullptr;
    if (!pZ) { cudaGetSymbolAddress((void**)&pZ, g_z);
               cudaGetSymbolAddress((void**)&pX, g_x0h); }
    __half* z1 = pZ;
    __half* z2 = pZ + (size_t)TOT_F;
    __half* z3 = pZ + (size_t)2 * TOT_F;

    // setup: deg atomics + fp16 cast fused, then CSR build
    k_deg_conv<<<gBig, T>>>(eu, ei, uemb, iemb);
    k_part    <<<N_PART, 256>>>();
    k_rowptr  <<<N_PART, 256>>>();
    k_fill    <<<gEThr, T>>>(eu, ei);

    // layers 1..3 materialized (fp16 storage, fp32 accumulation)
    k_spmm1h<<<gRow8, T>>>(pX, z1);
    k_spmmN <<<gRow8, T>>>(z1, z2);
    k_spmmN <<<gRow8, T>>>(z2, z3);

    // layer 4 fused into final (only batch rows needed)
    k_final<<<BATCH, 64>>>(users, items, uemb, iemb, z1, z2, z3, out);
}

// round 10
// speedup vs baseline: 1.0204x; 1.0204x over previous
#include <cuda_runtime.h>
#include <cuda_bf16.h>
#include <cuda_fp16.h>
#include <cstdint>

#define NUM_USERS 100000
#define NUM_ITEMS 50000
#define LATENT    64
#define N_EDGES   600000
#define BATCH     4096
#define N_NODES   (NUM_USERS + NUM_ITEMS)          // 150000
#define TOT_F     (N_NODES * LATENT)               // 9,600,000
#define USER_F    (NUM_USERS * LATENT)
#define N_DIR     (2 * N_EDGES)
#define N_PART    ((N_NODES + 255) / 256)          // 586

// ---------------- scratch (device globals) ----------------------------------
__device__ __half g_x0h[TOT_F];                    // fp16 x0 (19.2 MB)
__device__ __half g_z[3 * TOT_F];                  // z_1..z_3 fp16 (57.6 MB)
__device__ int    g_degi  [N_NODES];               // zero at entry (reset by spmm1h)
__device__ float  g_inv   [N_NODES];               // 1/sqrt(deg)
__device__ float  g_inv2  [N_NODES];               // 1/deg
__device__ int    g_part  [N_PART];
__device__ int    g_rowptr[N_NODES + 1];           // +1 sentinel = N_DIR
__device__ int2   g_slot  [N_EDGES];               // per-edge (slot_u, slot_v)
__device__ int    g_adj   [N_DIR];                 // src index only

// ---------------- kernels ---------------------------------------------------

// Fused: degree atomics WITH slot capture + fp16 cast of x0.
// The atomicAdd return value is the edge's slot within its row — recorded so
// k_fill needs no atomics. Relies on g_degi == 0 at entry (loader zero-init;
// k_spmm1h resets per run).
__global__ void k_deg_conv(const int* __restrict__ eu, const int* __restrict__ ei,
                           const float* __restrict__ uemb, const float* __restrict__ iemb) {
    int i = blockIdx.x * blockDim.x + threadIdx.x;   // 0 .. 1.2M-1
    const int n8 = TOT_F / 8;                        // 1,200,000
    if (i < n8) {
        int base = i * 8;
        const float4* src = (base < USER_F)
            ? reinterpret_cast<const float4*>(uemb + base)
            : reinterpret_cast<const float4*>(iemb + (base - USER_F));
        float4 a = src[0];
        float4 b = src[1];
        uint4 pack;
        __half2* h = reinterpret_cast<__half2*>(&pack);
        h[0] = __floats2half2_rn(a.x, a.y);
        h[1] = __floats2half2_rn(a.z, a.w);
        h[2] = __floats2half2_rn(b.x, b.y);
        h[3] = __floats2half2_rn(b.z, b.w);
        reinterpret_cast<uint4*>(g_x0h)[i] = pack;
    }
    if (i < N_EDGES) {
        int u = eu[i];
        int v = NUM_USERS + ei[i];
        int su = atomicAdd(&g_degi[u], 1);
        int sv = atomicAdd(&g_degi[v], 1);
        g_slot[i] = make_int2(su, sv);
    }
}

// per-256-chunk degree partial sums
__global__ void k_part() {
    __shared__ int s[256];
    int t = threadIdx.x;
    int n = blockIdx.x * 256 + t;
    s[t] = (n < N_NODES) ? g_degi[n] : 0;
    __syncthreads();
    for (int off = 128; off > 0; off >>= 1) {
        if (t < off) s[t] += s[t + off];
        __syncthreads();
    }
    if (t == 0) g_part[blockIdx.x] = s[0];
}

// rowptr + inv + inv2: block sums partials before it, then local 256-scan.
__global__ void k_rowptr() {
    __shared__ int s[256];
    __shared__ int base_s;
    int t   = threadIdx.x;
    int bid = blockIdx.x;

    int p = 0;
    for (int i = t; i < bid; i += 256) p += g_part[i];
    s[t] = p;
    __syncthreads();
    for (int off = 128; off > 0; off >>= 1) {
        if (t < off) s[t] += s[t + off];
        __syncthreads();
    }
    if (t == 0) base_s = s[0];
    __syncthreads();
    int base = base_s;

    int n = bid * 256 + t;
    int v = (n < N_NODES) ? g_degi[n] : 0;
    if (n < N_NODES) {
        float fd = (float)v;
        g_inv [n] = (v > 0) ? rsqrtf(fd)  : 0.f;
        g_inv2[n] = (v > 0) ? (1.0f / fd) : 0.f;
    }
    s[t] = v;
    __syncthreads();
    for (int off = 1; off < 256; off <<= 1) {
        int a = (t >= off) ? s[t - off] : 0;
        __syncthreads();
        s[t] += a;
        __syncthreads();
    }
    if (n < N_NODES) {
        g_rowptr[n] = base + s[t] - v;
        if (n == N_NODES - 1) g_rowptr[N_NODES] = N_DIR;
    }
}

// CSR fill: NO atomics — slots were captured during degree counting.
__global__ void k_fill(const int* __restrict__ eu, const int* __restrict__ ei) {
    int e = blockIdx.x * blockDim.x + threadIdx.x;
    if (e >= N_EDGES) return;
    int u = eu[e];
    int v = NUM_USERS + ei[e];
    int2 s = g_slot[e];
    g_adj[g_rowptr[u] + s.x] = v;
    g_adj[g_rowptr[v] + s.y] = u;
}

// Layer 1: z1[dst] = inv2[dst] * sum_src inv[src] * x0h[src]
// 8 lanes per row; lane owns 8 halves (uint4). fp32 accumulation.
// Also resets g_degi for the next graph replay.
__global__ void k_spmm1h(const __half* __restrict__ x, __half* __restrict__ y) {
    int gid = blockIdx.x * blockDim.x + threadIdx.x;
    if (gid < N_NODES) g_degi[gid] = 0;              // reset for next replay
    int row = gid >> 3;
    int sub = gid & 7;
    if (row >= N_NODES) return;

    int beg = g_rowptr[row];
    int cnt = g_rowptr[row + 1] - beg;
    float acc[8] = {0.f, 0.f, 0.f, 0.f, 0.f, 0.f, 0.f, 0.f};

    auto accum = [&](uint4 v, float ws) {
        const __half2* h = reinterpret_cast<const __half2*>(&v);
        #pragma unroll
        for (int q = 0; q < 4; q++) {
            float2 f = __half22float2(h[q]);
            acc[2 * q]     += ws * f.x;
            acc[2 * q + 1] += ws * f.y;
        }
    };

    int j = 0;
    for (; j + 1 < cnt; j += 2) {
        int s0 = g_adj[beg + j + 0];
        int s1 = g_adj[beg + j + 1];
        float w0 = g_inv[s0];
        float w1 = g_inv[s1];
        uint4 v0 = reinterpret_cast<const uint4*>(x + (size_t)s0 * LATENT)[sub];
        uint4 v1 = reinterpret_cast<const uint4*>(x + (size_t)s1 * LATENT)[sub];
        accum(v0, w0); accum(v1, w1);
    }
    if (j < cnt) {
        int s0 = g_adj[beg + j];
        float w0 = g_inv[s0];
        uint4 v0 = reinterpret_cast<const uint4*>(x + (size_t)s0 * LATENT)[sub];
        accum(v0, w0);
    }

    float s = g_inv2[row];
    uint4 outp;
    __half2* oh = reinterpret_cast<__half2*>(&outp);
    #pragma unroll
    for (int q = 0; q < 4; q++)
        oh[q] = __floats2half2_rn(acc[2 * q] * s, acc[2 * q + 1] * s);
    reinterpret_cast<uint4*>(y + (size_t)row * LATENT)[sub] = outp;
}

// Layers 2..3: z_{l+1}[dst] = inv2[dst] * sum_src z_l[src]   (fp16 in/out)
__global__ void k_spmmN(const __half* __restrict__ x, __half* __restrict__ y) {
    int gid = blockIdx.x * blockDim.x + threadIdx.x;
    int row = gid >> 3;
    int sub = gid & 7;
    if (row >= N_NODES) return;

    int beg = g_rowptr[row];
    int cnt = g_rowptr[row + 1] - beg;
    float acc[8] = {0.f, 0.f, 0.f, 0.f, 0.f, 0.f, 0.f, 0.f};

    auto accum = [&](uint4 v) {
        const __half2* h = reinterpret_cast<const __half2*>(&v);
        #pragma unroll
        for (int q = 0; q < 4; q++) {
            float2 f = __half22float2(h[q]);
            acc[2 * q]     += f.x;
            acc[2 * q + 1] += f.y;
        }
    };

    int j = 0;
    for (; j + 3 < cnt; j += 4) {
        int s0 = g_adj[beg + j + 0];
        int s1 = g_adj[beg + j + 1];
        int s2 = g_adj[beg + j + 2];
        int s3 = g_adj[beg + j + 3];
        uint4 v0 = reinterpret_cast<const uint4*>(x + (size_t)s0 * LATENT)[sub];
        uint4 v1 = reinterpret_cast<const uint4*>(x + (size_t)s1 * LATENT)[sub];
        uint4 v2 = reinterpret_cast<const uint4*>(x + (size_t)s2 * LATENT)[sub];
        uint4 v3 = reinterpret_cast<const uint4*>(x + (size_t)s3 * LATENT)[sub];
        accum(v0); accum(v1); accum(v2); accum(v3);
    }
    for (; j < cnt; j++) {
        int s0 = g_adj[beg + j];
        uint4 v0 = reinterpret_cast<const uint4*>(x + (size_t)s0 * LATENT)[sub];
        accum(v0);
    }

    float s = g_inv2[row];
    uint4 outp;
    __half2* oh = reinterpret_cast<__half2*>(&outp);
    #pragma unroll
    for (int q = 0; q < 4; q++)
        oh[q] = __floats2half2_rn(acc[2 * q] * s, acc[2 * q + 1] * s);
    reinterpret_cast<uint4*>(y + (size_t)row * LATENT)[sub] = outp;
}

// Fused layer-4 + final dot. One 64-thread block per batch pair.
__global__ void k_final(const int* __restrict__ users, const int* __restrict__ items,
                        const float* __restrict__ uemb, const float* __restrict__ iemb,
                        const __half* __restrict__ z1, const __half* __restrict__ z2,
                        const __half* __restrict__ z3,
                        float* __restrict__ out) {
    __shared__ float red[2];
    int b = blockIdx.x;
    int t = threadIdx.x;            // 0..63 = column

    int u  = users[b];
    int it = NUM_USERS + items[b];

    int bu = g_rowptr[u];
    int cu = g_rowptr[u + 1] - bu;
    int bi = g_rowptr[it];
    int ci = g_rowptr[it + 1] - bi;

    float z4u = 0.f;
    for (int j = 0; j < cu; j++) {
        int s = g_adj[bu + j];
        z4u += __half2float(z3[(size_t)s * LATENT + t]);
    }
    z4u *= g_inv2[u];
    size_t ou = (size_t)u * LATENT + t;
    float zu = __half2float(z1[ou]) + __half2float(z2[ou]) + __half2float(z3[ou]) + z4u;
    float su = uemb[ou] + sqrtf((float)cu) * zu;

    float z4i = 0.f;
    for (int j = 0; j < ci; j++) {
        int s = g_adj[bi + j];
        z4i += __half2float(z3[(size_t)s * LATENT + t]);
    }
    z4i *= g_inv2[it];
    size_t oi = (size_t)it * LATENT + t;
    float zi = __half2float(z1[oi]) + __half2float(z2[oi]) + __half2float(z3[oi]) + z4i;
    float si = iemb[(size_t)(it - NUM_USERS) * LATENT + t] + sqrtf((float)ci) * zi;

    float dot = su * si;
    #pragma unroll
    for (int off = 16; off > 0; off >>= 1)
        dot += __shfl_xor_sync(0xffffffffu, dot, off);
    if ((t & 31) == 0) red[t >> 5] = dot;
    __syncthreads();
    if (t == 0) out[b] = (red[0] + red[1]) * (1.0f / 25.0f);
}

// ---------------- launch ----------------------------------------------------
extern "C" void kernel_launch(void* const* d_in, const int* in_sizes, int n_in,
                              void* d_out, int out_size) {
    const int*   users = (const int*)  d_in[0];
    const int*   items = (const int*)  d_in[1];
    const int*   eu    = (const int*)  d_in[2];
    const int*   ei    = (const int*)  d_in[3];
    const float* uemb  = (const float*)d_in[4];
    const float* iemb  = (const float*)d_in[5];
    float*       out   = (float*)d_out;

    const int T = 256;
    const int n8     = TOT_F / 8;                    // 1.2M
    const int gBig   = (n8 + T - 1) / T;
    const int gEdge  = (N_EDGES + T - 1) / T;
    const int gRow8  = (N_NODES * 8 + T - 1) / T;

    static __half* pZ = nullptr; static __half* pX = nullptr;
    if (!pZ) { cudaGetSymbolAddress((void**)&pZ, g_z);
               cudaGetSymbolAddress((void**)&pX, g_x0h); }
    __half* z1 = pZ;
    __half* z2 = pZ + (size_t)TOT_F;
    __half* z3 = pZ + (size_t)2 * TOT_F;

    // setup: deg atomics (slot capture) + fp16 cast fused, then CSR build
    k_deg_conv<<<gBig, T>>>(eu, ei, uemb, iemb);
    k_part    <<<N_PART, 256>>>();
    k_rowptr  <<<N_PART, 256>>>();
    k_fill    <<<gEdge, T>>>(eu, ei);

    // layers 1..3 materialized (fp16 storage, fp32 accumulation)
    k_spmm1h<<<gRow8, T>>>(pX, z1);
    k_spmmN <<<gRow8, T>>>(z1, z2);
    k_spmmN <<<gRow8, T>>>(z2, z3);

    // layer 4 fused into final (only batch rows needed)
    k_final<<<BATCH, 64>>>(users, items, uemb, iemb, z1, z2, z3, out);
}